// round 5
// baseline (speedup 1.0000x reference)
#include <cuda_runtime.h>
#include <cstdint>

#define NT      9
#define SEQ     512
#define BATCH   64
#define EMB     1024
#define CHUNKS  8
#define CHUNK_LEN 64

#define L2E 1.4426950408889634f
#define LN2 0.6931471805599453f

// tags dtype flag: 1 = int64, 0 = int32
__device__ int g_tags64;

__device__ __forceinline__ void ffma2(unsigned long long& acc,
                                      unsigned long long a,
                                      unsigned long long b)
{
    asm("fma.rn.f32x2 %0, %1, %2, %3;" : "=l"(acc) : "l"(a), "l"(b), "l"(acc));
}
__device__ __forceinline__ unsigned long long dup2(float x)
{
    unsigned long long r; asm("mov.b64 %0, {%1,%1};" : "=l"(r) : "f"(x)); return r;
}
__device__ __forceinline__ float fast_ex2(float x)
{
    float r; asm("ex2.approx.ftz.f32 %0, %1;" : "=f"(r) : "f"(x)); return r;
}
__device__ __forceinline__ float fast_lg2(float x)
{
    float r; asm("lg2.approx.ftz.f32 %0, %1;" : "=f"(r) : "f"(x)); return r;
}

// ---------------------------------------------------------------------------
// Kernel 1: emission = log_softmax(embed @ W^T + b)
// grid 512, block 256. Block covers 64 rows; K in 16 tiles of 64 cols.
// Thread = (row-pair {lane, lane+32}, 8-col K-slice sl=warp). Tiles staged
// COALESCED into smem (row stride 68 floats = 17x16B, conflict-free for
// LDS.128); next tile prefetched into registers during compute. W tile in
// smem [e][12] pair layout, warp-broadcast, amortized over 2 rows/thread.
// ---------------------------------------------------------------------------
__global__ __launch_bounds__(256) void emis7(
    const float* __restrict__ embed,
    const float* __restrict__ W,
    const float* __restrict__ bias,
    const unsigned* __restrict__ tags_words,
    float* __restrict__ out)
{
    __shared__ __align__(16) float sE[64 * 73];   // staging stride 68; red stride 73
    __shared__ __align__(16) float sWt[64 * 12];  // 3 KB

    const int tid = threadIdx.x;

    if (blockIdx.x == 0) {
        __shared__ int s_any;
        if (tid == 0) s_any = 0;
        __syncthreads();
        int nz = 0;
        for (int qq = tid; qq < 2048; qq += 256)
            nz |= (tags_words[2 * qq + 1] != 0u);
        if (nz) atomicOr(&s_any, 1);
        __syncthreads();
        if (tid == 0) {
            g_tags64 = s_any ? 0 : 1;
            out[0] = 0.0f;               // ll accumulator
        }
    }

    const int sl   = tid >> 5;       // K-slice 0..7 (warp id), 8 cols per tile
    const int lane = tid & 31;
    const int rowBase = blockIdx.x * 64;

    // -------- prefetch tile 0 --------
    float4 pe[4];
    float  pw[3];
    {
        const float* gsrc = embed + (size_t)rowBase * EMB;
#pragma unroll
        for (int it = 0; it < 4; ++it) {
            int idx = it * 256 + tid;            // 1024 float4 slots: 64 rows x 16
            int r2 = idx >> 4, cc = (idx & 15) * 4;
            pe[it] = *(const float4*)(gsrc + (size_t)r2 * EMB + cc);
        }
#pragma unroll
        for (int it = 0; it < 3; ++it) {
            int idx = it * 256 + tid;
            if (idx < 576) {
                int t = idx >> 6, e = idx & 63;
                pw[it] = W[t * EMB + e];
            }
        }
    }

    unsigned long long a01_0 = 0ull, a23_0 = 0ull, a45_0 = 0ull, a67_0 = 0ull;
    unsigned long long a01_1 = 0ull, a23_1 = 0ull, a45_1 = 0ull, a67_1 = 0ull;
    float a8_0 = 0.0f, a8_1 = 0.0f;

    for (int tile = 0; tile < 16; ++tile) {
        __syncthreads();             // previous compute done reading smem
#pragma unroll
        for (int it = 0; it < 4; ++it) {
            int idx = it * 256 + tid;
            int r2 = idx >> 4, cc = (idx & 15) * 4;
            *(float4*)&sE[r2 * 68 + cc] = pe[it];
        }
#pragma unroll
        for (int it = 0; it < 3; ++it) {
            int idx = it * 256 + tid;
            if (idx < 576) {
                int t = idx >> 6, e = idx & 63;
                sWt[e * 12 + t] = pw[it];
            }
        }
        __syncthreads();             // tile ready

        // prefetch next tile
        if (tile < 15) {
            const float* gsrc = embed + (size_t)rowBase * EMB + (tile + 1) * 64;
#pragma unroll
            for (int it = 0; it < 4; ++it) {
                int idx = it * 256 + tid;
                int r2 = idx >> 4, cc = (idx & 15) * 4;
                pe[it] = *(const float4*)(gsrc + (size_t)r2 * EMB + cc);
            }
#pragma unroll
            for (int it = 0; it < 3; ++it) {
                int idx = it * 256 + tid;
                if (idx < 576) {
                    int t = idx >> 6, e = idx & 63;
                    pw[it] = W[t * EMB + (tile + 1) * 64 + e];
                }
            }
        }

        // compute: 8 cols of this tile (slice sl) x 2 rows
        const float* xr0 = &sE[lane * 68 + sl * 8];
        const float* xr1 = &sE[(lane + 32) * 68 + sl * 8];
        const float* wq  = &sWt[(sl * 8) * 12];
#pragma unroll
        for (int e4 = 0; e4 < 8; e4 += 4) {
            float4 xa4 = *(const float4*)(xr0 + e4);
            float4 xb4 = *(const float4*)(xr1 + e4);
#pragma unroll
            for (int u = 0; u < 4; ++u) {
                float xa = (u == 0) ? xa4.x : (u == 1) ? xa4.y : (u == 2) ? xa4.z : xa4.w;
                float xb = (u == 0) ? xb4.x : (u == 1) ? xb4.y : (u == 2) ? xb4.z : xb4.w;
                const float* we = wq + (e4 + u) * 12;
                ulonglong2 wA = *(const ulonglong2*)we;        // {w0,w1},{w2,w3}
                ulonglong2 wB = *(const ulonglong2*)(we + 4);  // {w4,w5},{w6,w7}
                float w8 = we[8];
                unsigned long long da = dup2(xa);
                unsigned long long db = dup2(xb);
                ffma2(a01_0, da, wA.x); ffma2(a23_0, da, wA.y);
                ffma2(a45_0, da, wB.x); ffma2(a67_0, da, wB.y);
                a8_0 = fmaf(xa, w8, a8_0);
                ffma2(a01_1, db, wA.x); ffma2(a23_1, db, wA.y);
                ffma2(a45_1, db, wB.x); ffma2(a67_1, db, wB.y);
                a8_1 = fmaf(xb, w8, a8_1);
            }
        }
    }

    // -------- reduction across slices + log_softmax --------
    __syncthreads();                 // done with sE as tile buffer
    float* red = sE;                 // red[row][73]: [sl*9 + t]
    {
        float2 f;
        float* r0 = &red[lane * 73 + sl * 9];
        f = *(float2*)&a01_0; r0[0] = f.x; r0[1] = f.y;
        f = *(float2*)&a23_0; r0[2] = f.x; r0[3] = f.y;
        f = *(float2*)&a45_0; r0[4] = f.x; r0[5] = f.y;
        f = *(float2*)&a67_0; r0[6] = f.x; r0[7] = f.y;
        r0[8] = a8_0;
        float* r1 = &red[(lane + 32) * 73 + sl * 9];
        f = *(float2*)&a01_1; r1[0] = f.x; r1[1] = f.y;
        f = *(float2*)&a23_1; r1[2] = f.x; r1[3] = f.y;
        f = *(float2*)&a45_1; r1[4] = f.x; r1[5] = f.y;
        f = *(float2*)&a67_1; r1[6] = f.x; r1[7] = f.y;
        r1[8] = a8_1;
    }
    __syncthreads();

    if (tid < 64) {
        const float* rp = &red[tid * 73];
        float acc[NT];
#pragma unroll
        for (int t = 0; t < NT; t++) {
            float s = bias[t];
#pragma unroll
            for (int qq = 0; qq < 8; qq++) s += rp[qq * 9 + t];
            acc[t] = s;
        }

        float mx = acc[0];
#pragma unroll
        for (int t = 1; t < NT; t++) mx = fmaxf(mx, acc[t]);
        float s = 0.0f;
#pragma unroll
        for (int t = 0; t < NT; t++) s += fast_ex2((acc[t] - mx) * L2E);
        float lse = fmaf(fast_lg2(s), LN2, mx);

        float* o = out + 1 + (size_t)(rowBase + tid) * NT;
#pragma unroll
        for (int t = 0; t < NT; t++) o[t] = acc[t] - lse;
    }
}

// ---------------------------------------------------------------------------
// Kernel 2 (fused CRF): one block per batch, 768 threads = 8 chunks x 3 warps.
// Whole sequence's emissions + mask staged in smem once. Phase 1: 8 parallel
// chunk scans (9-lane row-scans via shfl, exp-trans factorization).
// Phase 2: numerator. Phase 3: warp 0 combines the 8 chunk matrices,
// computes denominator, atomicAdd of the log-likelihood.
// ---------------------------------------------------------------------------
__global__ __launch_bounds__(768) void crf_fused(
    float* __restrict__ outbuf,
    const void* __restrict__ tags,
    const int*  __restrict__ mask,
    const float* __restrict__ startT,
    const float* __restrict__ endT,
    const float* __restrict__ trans)
{
    const float* emis = outbuf + 1;
    const int b   = blockIdx.x;
    const int tid = threadIdx.x;
    const int warp = tid >> 5;
    const int lane = tid & 31;

    __shared__ float sEm[SEQ * NT];      // 18.4 KB
    __shared__ int   sMk[SEQ];
    __shared__ float sTr[81];
    __shared__ float sM[CHUNKS * 81];
    __shared__ float s_accf;
    __shared__ int   s_msum;
    __shared__ float s_num;

    if (tid == 0) { s_accf = 0.0f; s_msum = 0; }

    const float* em_b = emis + (size_t)b * SEQ * NT;
    const int*   mk   = mask + b * SEQ;
    for (int idx = tid; idx < SEQ * NT; idx += 768) sEm[idx] = em_b[idx];
    for (int idx = tid; idx < SEQ;      idx += 768) sMk[idx] = mk[idx];
    if (tid < 81) sTr[tid] = trans[tid];
    __syncthreads();

    // ---- phase 1: chunk scans ----
    {
        const int c   = warp / 3;            // chunk 0..7
        const int wim = warp - c * 3;        // warp-in-chunk 0..2
        int g = lane / 9; if (g > 2) g = 2;  // lanes 27..31 mirror group 2
        const int j = lane % 9;
        const int i = wim * 3 + g;
        const int rowbase = g * 9;

        float E2[9];
#pragma unroll
        for (int k = 0; k < 9; k++) E2[k] = fast_ex2(sTr[k * 9 + j] * L2E);
        const float tij = sTr[i * 9 + j];

        float v = (j == i) ? 0.0f : -1e30f;
        bool started = false;

        const int t0 = 1 + c * CHUNK_LEN;
        const int t1 = min(SEQ, t0 + CHUNK_LEN);

        for (int t = t0; t < t1; ++t) {
            const int   m  = sMk[t];
            const float ev = sEm[t * NT + j];
            if (m) {
                if (!started) {
                    v = tij + ev;
                    started = true;
                } else {
                    float r = __shfl_sync(0xffffffffu, v, rowbase);
                    float e = fast_ex2((v - r) * L2E);
                    float s = 0.0f;
#pragma unroll
                    for (int k = 0; k < 9; k++)
                        s = fmaf(__shfl_sync(0xffffffffu, e, rowbase + k), E2[k], s);
                    v = fmaf(fast_lg2(s), LN2, r) + ev;
                }
            }
        }
        if (lane < 27) sM[c * 81 + i * 9 + j] = v;
    }

    // ---- phase 2: numerator ----
    {
        const long long* t64 = (const long long*)tags;
        const int*       t32 = (const int*)tags;
        const int is64 = g_tags64;

        float acc = 0.0f;
        int   msum = 0;
        if (tid < SEQ) {
            const int s = tid;
            const int m = sMk[s];
            msum = m;
            if (s >= 1) {
                int tp  = is64 ? (int)t64[b * SEQ + s - 1] : t32[b * SEQ + s - 1];
                int tcu = is64 ? (int)t64[b * SEQ + s]     : t32[b * SEQ + s];
                acc = (float)m * (sTr[tp * 9 + tcu] + sEm[s * NT + tcu]);
            }
        }
#pragma unroll
        for (int o = 16; o > 0; o >>= 1) {
            acc  += __shfl_down_sync(0xffffffffu, acc, o);
            msum += __shfl_down_sync(0xffffffffu, msum, o);
        }
        if (lane == 0) {
            atomicAdd(&s_accf, acc);
            atomicAdd(&s_msum, msum);
        }
    }
    __syncthreads();

    if (tid == 0) {
        const long long* t64 = (const long long*)tags;
        const int*       t32 = (const int*)tags;
        const int is64 = g_tags64;
        int tg0  = is64 ? (int)t64[b * SEQ] : t32[b * SEQ];
        int last = s_msum - 1;
        int tl   = is64 ? (int)t64[b * SEQ + last] : t32[b * SEQ + last];
        s_num = s_accf + startT[tg0] + sEm[tg0] + endT[tl];
    }
    __syncthreads();

    // ---- phase 3: combine + denominator (warp 0) ----
    if (tid < 32) {
        const int j = tid;
        float v = (j < 9) ? (startT[j] + sEm[j]) : -1e30f;
        for (int c = 0; c < CHUNKS; c++) {
            const float* Mc = sM + c * 81;
            float vals[9];
#pragma unroll
            for (int i2 = 0; i2 < 9; i2++) {
                float sv = __shfl_sync(0xffffffffu, v, i2);
                vals[i2] = sv + ((j < 9) ? Mc[i2 * 9 + j] : 0.0f);
            }
            float nv = -1e30f;
            if (j < 9) {
                float mx = vals[0];
#pragma unroll
                for (int i2 = 1; i2 < 9; i2++) mx = fmaxf(mx, vals[i2]);
                float s = 0.0f;
#pragma unroll
                for (int i2 = 0; i2 < 9; i2++) s += fast_ex2((vals[i2] - mx) * L2E);
                nv = fmaf(fast_lg2(s), LN2, mx);
            }
            v = nv;
        }
        float x = (j < 9) ? v + endT[j] : -1e30f;
        float mx = x;
#pragma unroll
        for (int o = 16; o > 0; o >>= 1) mx = fmaxf(mx, __shfl_xor_sync(0xffffffffu, mx, o));
        float e = (j < 9) ? fast_ex2((x - mx) * L2E) : 0.0f;
#pragma unroll
        for (int o = 16; o > 0; o >>= 1) e += __shfl_xor_sync(0xffffffffu, e, o);
        if (tid == 0) {
            float den = fmaf(fast_lg2(e), LN2, mx);
            atomicAdd(outbuf, s_num - den);
        }
    }
}

// ---------------------------------------------------------------------------
extern "C" void kernel_launch(void* const* d_in, const int* in_sizes, int n_in,
                              void* d_out, int out_size)
{
    const float* embed  = (const float*)d_in[0];
    const void*  tags   = d_in[1];
    const int*   mask   = (const int*)d_in[2];
    const float* W      = (const float*)d_in[3];
    const float* bias   = (const float*)d_in[4];
    const float* startT = (const float*)d_in[5];
    const float* endT   = (const float*)d_in[6];
    const float* trans  = (const float*)d_in[7];
    float* out = (float*)d_out;

    emis7<<<(BATCH * SEQ) / 64, 256>>>(embed, W, bias,
                                       (const unsigned*)tags, out);
    crf_fused<<<BATCH, 768>>>(out, tags, mask, startT, endT, trans);
}